// round 1
// baseline (speedup 1.0000x reference)
#include <cuda_runtime.h>
#include <math.h>

#define T_STEPS 4
#define ROWS    8192      // B*N = 8*1024
#define DDIM    512
#define FDIM    2048
#define MTOT    (T_STEPS*ROWS)   // 32768

// Scratch (device globals -- no runtime allocation allowed)
__device__ float g_h[(size_t)T_STEPS * ROWS * FDIM];  // 256 MiB: hidden acts / spikes
__device__ float g_y[(size_t)T_STEPS * ROWS * DDIM];  //  64 MiB: layer-2 preacts

// ---------------------------------------------------------------------------
// Classic 128x128x16 fp32 SGEMM with fused bias. C[M,N] = A[M,K]*B[K,N] + bias
// 256 threads, 8x8 per thread. Sequential-K accumulation (numerics ~ BLAS).
// All dims here are multiples of the tile sizes, so no bounds checks.
// ---------------------------------------------------------------------------
__global__ __launch_bounds__(256, 2)
void sgemm_bias_128(const float* __restrict__ A, const float* __restrict__ B,
                    const float* __restrict__ bias, float* __restrict__ C,
                    int M, int N, int K) {
    const int BK = 16;
    __shared__ float As[16][128];
    __shared__ float Bs[16][128];

    const int tid = threadIdx.x;
    const int bm  = blockIdx.y * 128;
    const int bn  = blockIdx.x * 128;
    const int tr  = (tid >> 4) * 8;   // 0..120
    const int tc  = (tid & 15) * 8;   // 0..120

    float acc[8][8];
#pragma unroll
    for (int i = 0; i < 8; i++)
#pragma unroll
        for (int j = 0; j < 8; j++) acc[i][j] = 0.0f;

    const float* Aptr = A + (size_t)bm * K;
    const float* Bptr = B + bn;

    for (int kt = 0; kt < K; kt += BK) {
        // Load A tile 128x16 (512 float4), transposed into As[k][m]
#pragma unroll
        for (int i = 0; i < 2; i++) {
            int id = tid + i * 256;
            int r  = id >> 2;
            int c4 = (id & 3) << 2;
            float4 v = *(const float4*)(Aptr + (size_t)r * K + kt + c4);
            As[c4 + 0][r] = v.x;
            As[c4 + 1][r] = v.y;
            As[c4 + 2][r] = v.z;
            As[c4 + 3][r] = v.w;
        }
        // Load B tile 16x128 (512 float4), direct
#pragma unroll
        for (int i = 0; i < 2; i++) {
            int id = tid + i * 256;
            int r  = id >> 5;
            int c  = (id & 31) << 2;
            *(float4*)&Bs[r][c] = *(const float4*)(Bptr + (size_t)(kt + r) * N + c);
        }
        __syncthreads();

#pragma unroll
        for (int k = 0; k < BK; k++) {
            float a[8], b[8];
#pragma unroll
            for (int i = 0; i < 8; i++) a[i] = As[k][tr + i];
#pragma unroll
            for (int j = 0; j < 8; j++) b[j] = Bs[k][tc + j];
#pragma unroll
            for (int i = 0; i < 8; i++)
#pragma unroll
                for (int j = 0; j < 8; j++)
                    acc[i][j] = fmaf(a[i], b[j], acc[i][j]);
        }
        __syncthreads();
    }

#pragma unroll
    for (int i = 0; i < 8; i++) {
        float* Crow = C + (size_t)(bm + tr + i) * N + bn + tc;
#pragma unroll
        for (int j = 0; j < 8; j++)
            Crow[j] = acc[i][j] + bias[bn + tc + j];
    }
}

// ---------------------------------------------------------------------------
// Block-wide sum reduction
// ---------------------------------------------------------------------------
template <int NT>
__device__ __forceinline__ float block_sum(float val, float* sh) {
    const int lane = threadIdx.x & 31;
    const int warp = threadIdx.x >> 5;
#pragma unroll
    for (int o = 16; o > 0; o >>= 1) val += __shfl_down_sync(0xffffffffu, val, o);
    if (lane == 0) sh[warp] = val;
    __syncthreads();
    const int NW = NT / 32;
    if (warp == 0) {
        float v = (lane < NW) ? sh[lane] : 0.0f;
#pragma unroll
        for (int o = 16; o > 0; o >>= 1) v += __shfl_down_sync(0xffffffffu, v, o);
        if (lane == 0) sh[0] = v;
    }
    __syncthreads();
    float r = sh[0];
    __syncthreads();
    return r;
}

// ---------------------------------------------------------------------------
// Fused LayerNorm (per row, per t) + LIF scan across T (in registers).
// One CTA per (b,n) row. Reads [T][FD] for that row, writes spikes.
// Two-pass variance to match reference numerics; exact 1/sqrtf.
// ---------------------------------------------------------------------------
template <int FD, int NT>
__global__ void ln_lif_kernel(const float* __restrict__ in,
                              const float* __restrict__ w,
                              const float* __restrict__ bvec,
                              const float* __restrict__ betap,
                              float* __restrict__ out) {
    const int VPT = FD / NT;
    const int r   = blockIdx.x;
    const int tid = threadIdx.x;
    __shared__ float sh[32];

    float v[T_STEPS][VPT];
    float wv[VPT], bv[VPT];
#pragma unroll
    for (int j = 0; j < VPT; j++) {
        wv[j] = w[tid + j * NT];
        bv[j] = bvec[tid + j * NT];
    }
#pragma unroll
    for (int t = 0; t < T_STEPS; t++) {
        const float* rowp = in + ((size_t)t * ROWS + r) * FD;
#pragma unroll
        for (int j = 0; j < VPT; j++) v[t][j] = rowp[tid + j * NT];
    }

#pragma unroll
    for (int t = 0; t < T_STEPS; t++) {
        float s = 0.0f;
#pragma unroll
        for (int j = 0; j < VPT; j++) s += v[t][j];
        s = block_sum<NT>(s, sh);
        const float mu = s * (1.0f / FD);

        float q = 0.0f;
#pragma unroll
        for (int j = 0; j < VPT; j++) {
            float d = v[t][j] - mu;
            q += d * d;
        }
        q = block_sum<NT>(q, sh);
        const float inv = 1.0f / sqrtf(q * (1.0f / FD) + 1e-5f);

#pragma unroll
        for (int j = 0; j < VPT; j++)
            v[t][j] = (v[t][j] - mu) * inv * wv[j] + bv[j];
    }

    // LIF scan across T in registers (soft reset, threshold 1.0)
    const float beta = *betap;
#pragma unroll
    for (int j = 0; j < VPT; j++) {
        float mem = 0.0f;
#pragma unroll
        for (int t = 0; t < T_STEPS; t++) {
            mem = fmaf(beta, mem, v[t][j]);
            float spk = (mem - 1.0f) > 0.0f ? 1.0f : 0.0f;
            mem -= spk;
            v[t][j] = spk;
        }
    }

#pragma unroll
    for (int t = 0; t < T_STEPS; t++) {
        float* rowp = out + ((size_t)t * ROWS + r) * FD;
#pragma unroll
        for (int j = 0; j < VPT; j++) rowp[tid + j * NT] = v[t][j];
    }
}

// ---------------------------------------------------------------------------
extern "C" void kernel_launch(void* const* d_in, const int* in_sizes, int n_in,
                              void* d_out, int out_size) {
    const float* x     = (const float*)d_in[0];
    const float* W1    = (const float*)d_in[1];
    const float* b1    = (const float*)d_in[2];
    const float* ln1w  = (const float*)d_in[3];
    const float* ln1b  = (const float*)d_in[4];
    const float* beta1 = (const float*)d_in[5];
    const float* W2    = (const float*)d_in[6];
    const float* b2    = (const float*)d_in[7];
    const float* ln2w  = (const float*)d_in[8];
    const float* ln2b  = (const float*)d_in[9];
    const float* beta2 = (const float*)d_in[10];
    float* out = (float*)d_out;

    float *h, *y;
    cudaGetSymbolAddress((void**)&h, g_h);
    cudaGetSymbolAddress((void**)&y, g_y);

    // GEMM1: [32768,512] x [512,2048] + b1 -> h
    {
        dim3 grid(FDIM / 128, MTOT / 128);
        sgemm_bias_128<<<grid, 256>>>(x, W1, b1, h, MTOT, FDIM, DDIM);
    }
    // LN1 + LIF1 (in place: h preacts -> h spikes)
    ln_lif_kernel<FDIM, 256><<<ROWS, 256>>>(h, ln1w, ln1b, beta1, h);

    // GEMM2: [32768,2048] x [2048,512] + b2 -> y
    {
        dim3 grid(DDIM / 128, MTOT / 128);
        sgemm_bias_128<<<grid, 256>>>(h, W2, b2, y, MTOT, DDIM, FDIM);
    }
    // LN2 + LIF2 -> d_out
    ln_lif_kernel<DDIM, 128><<<ROWS, 128>>>(y, ln2w, ln2b, beta2, out);
}

// round 2
// speedup vs baseline: 1.6907x; 1.6907x over previous
#include <cuda_runtime.h>
#include <math.h>

#define T_STEPS 4
#define ROWS    8192      // B*N = 8*1024
#define DDIM    512
#define FDIM    2048
#define MTOT    (T_STEPS*ROWS)   // 32768

typedef unsigned long long u64;

// Scratch (device globals -- no runtime allocation allowed)
__device__ float g_h[(size_t)T_STEPS * ROWS * FDIM];  // 256 MiB: hidden acts / spikes
__device__ float g_y[(size_t)T_STEPS * ROWS * DDIM];  //  64 MiB: layer-2 preacts

// ---- packed f32x2 helpers (sm_100+: fma.rn.f32x2; ptxas never emits it) ----
__device__ __forceinline__ u64 pack2(float lo, float hi) {
    u64 r; asm("mov.b64 %0, {%1, %2};" : "=l"(r) : "f"(lo), "f"(hi)); return r;
}
__device__ __forceinline__ void unpack2(u64 v, float& lo, float& hi) {
    asm("mov.b64 {%0, %1}, %2;" : "=f"(lo), "=f"(hi) : "l"(v));
}
#define FFMA2(d, a, b) \
    asm("fma.rn.f32x2 %0, %1, %2, %0;" : "+l"(d) : "l"(a), "l"(b))

// ---------------------------------------------------------------------------
// 128x128x16 fp32 SGEMM with fused bias, inner loop in packed f32x2 FMAs.
// C[M,N] = A[M,K]*B[K,N] + bias. 256 threads, 8x8 per thread (as 8x4 f32x2).
// Per-element accumulation order identical to scalar version (k sequential,
// each f32x2 lane an independent RN fp32 FMA) -> bit-identical results.
// ---------------------------------------------------------------------------
__global__ __launch_bounds__(256, 2)
void sgemm_bias_128(const float* __restrict__ A, const float* __restrict__ B,
                    const float* __restrict__ bias, float* __restrict__ C,
                    int M, int N, int K) {
    const int BK = 16;
    __shared__ float As[16][128];
    __shared__ float Bs[16][128];

    const int tid = threadIdx.x;
    const int bm  = blockIdx.y * 128;
    const int bn  = blockIdx.x * 128;
    const int tr  = (tid >> 4) * 8;   // 0..120
    const int tc  = (tid & 15) * 8;   // 0..120

    u64 acc[8][4];
#pragma unroll
    for (int i = 0; i < 8; i++)
#pragma unroll
        for (int j = 0; j < 4; j++) acc[i][j] = 0ull;

    const float* Aptr = A + (size_t)bm * K;
    const float* Bptr = B + bn;

    for (int kt = 0; kt < K; kt += BK) {
        // Load A tile 128x16 (512 float4), transposed into As[k][m]
#pragma unroll
        for (int i = 0; i < 2; i++) {
            int id = tid + i * 256;
            int r  = id >> 2;
            int c4 = (id & 3) << 2;
            float4 v = *(const float4*)(Aptr + (size_t)r * K + kt + c4);
            As[c4 + 0][r] = v.x;
            As[c4 + 1][r] = v.y;
            As[c4 + 2][r] = v.z;
            As[c4 + 3][r] = v.w;
        }
        // Load B tile 16x128 (512 float4), direct
#pragma unroll
        for (int i = 0; i < 2; i++) {
            int id = tid + i * 256;
            int r  = id >> 5;
            int c  = (id & 31) << 2;
            *(float4*)&Bs[r][c] = *(const float4*)(Bptr + (size_t)(kt + r) * N + c);
        }
        __syncthreads();

#pragma unroll
        for (int k = 0; k < BK; k++) {
            // A fragment: 8 scalars, broadcast-packed into f32x2
            float4 av0 = *(const float4*)&As[k][tr];
            float4 av1 = *(const float4*)&As[k][tr + 4];
            u64 a2[8];
            a2[0] = pack2(av0.x, av0.x);
            a2[1] = pack2(av0.y, av0.y);
            a2[2] = pack2(av0.z, av0.z);
            a2[3] = pack2(av0.w, av0.w);
            a2[4] = pack2(av1.x, av1.x);
            a2[5] = pack2(av1.y, av1.y);
            a2[6] = pack2(av1.z, av1.z);
            a2[7] = pack2(av1.w, av1.w);
            // B fragment: 4 packed pairs (contiguous, already interleaved right)
            const ulonglong2* bp = (const ulonglong2*)&Bs[k][tc];
            ulonglong2 bv0 = bp[0];
            ulonglong2 bv1 = bp[1];
            u64 b2[4] = {bv0.x, bv0.y, bv1.x, bv1.y};

#pragma unroll
            for (int i = 0; i < 8; i++)
#pragma unroll
                for (int j = 0; j < 4; j++)
                    FFMA2(acc[i][j], a2[i], b2[j]);
        }
        __syncthreads();
    }

#pragma unroll
    for (int i = 0; i < 8; i++) {
        float* Crow = C + (size_t)(bm + tr + i) * N + bn + tc;
#pragma unroll
        for (int j = 0; j < 4; j++) {
            float lo, hi;
            unpack2(acc[i][j], lo, hi);
            Crow[2 * j + 0] = lo + bias[bn + tc + 2 * j + 0];
            Crow[2 * j + 1] = hi + bias[bn + tc + 2 * j + 1];
        }
    }
}

// ---------------------------------------------------------------------------
// Block-wide sum reduction
// ---------------------------------------------------------------------------
template <int NT>
__device__ __forceinline__ float block_sum(float val, float* sh) {
    const int lane = threadIdx.x & 31;
    const int warp = threadIdx.x >> 5;
#pragma unroll
    for (int o = 16; o > 0; o >>= 1) val += __shfl_down_sync(0xffffffffu, val, o);
    if (lane == 0) sh[warp] = val;
    __syncthreads();
    const int NW = NT / 32;
    if (warp == 0) {
        float v = (lane < NW) ? sh[lane] : 0.0f;
#pragma unroll
        for (int o = 16; o > 0; o >>= 1) v += __shfl_down_sync(0xffffffffu, v, o);
        if (lane == 0) sh[0] = v;
    }
    __syncthreads();
    float r = sh[0];
    __syncthreads();
    return r;
}

// ---------------------------------------------------------------------------
// Fused LayerNorm (per row, per t) + LIF scan across T (in registers).
// ---------------------------------------------------------------------------
template <int FD, int NT>
__global__ void ln_lif_kernel(const float* __restrict__ in,
                              const float* __restrict__ w,
                              const float* __restrict__ bvec,
                              const float* __restrict__ betap,
                              float* __restrict__ out) {
    const int VPT = FD / NT;
    const int r   = blockIdx.x;
    const int tid = threadIdx.x;
    __shared__ float sh[32];

    float v[T_STEPS][VPT];
    float wv[VPT], bv[VPT];
#pragma unroll
    for (int j = 0; j < VPT; j++) {
        wv[j] = w[tid + j * NT];
        bv[j] = bvec[tid + j * NT];
    }
#pragma unroll
    for (int t = 0; t < T_STEPS; t++) {
        const float* rowp = in + ((size_t)t * ROWS + r) * FD;
#pragma unroll
        for (int j = 0; j < VPT; j++) v[t][j] = rowp[tid + j * NT];
    }

#pragma unroll
    for (int t = 0; t < T_STEPS; t++) {
        float s = 0.0f;
#pragma unroll
        for (int j = 0; j < VPT; j++) s += v[t][j];
        s = block_sum<NT>(s, sh);
        const float mu = s * (1.0f / FD);

        float q = 0.0f;
#pragma unroll
        for (int j = 0; j < VPT; j++) {
            float d = v[t][j] - mu;
            q += d * d;
        }
        q = block_sum<NT>(q, sh);
        const float inv = 1.0f / sqrtf(q * (1.0f / FD) + 1e-5f);

#pragma unroll
        for (int j = 0; j < VPT; j++)
            v[t][j] = (v[t][j] - mu) * inv * wv[j] + bv[j];
    }

    // LIF scan across T in registers (soft reset, threshold 1.0)
    const float beta = *betap;
#pragma unroll
    for (int j = 0; j < VPT; j++) {
        float mem = 0.0f;
#pragma unroll
        for (int t = 0; t < T_STEPS; t++) {
            mem = fmaf(beta, mem, v[t][j]);
            float spk = (mem - 1.0f) > 0.0f ? 1.0f : 0.0f;
            mem -= spk;
            v[t][j] = spk;
        }
    }

#pragma unroll
    for (int t = 0; t < T_STEPS; t++) {
        float* rowp = out + ((size_t)t * ROWS + r) * FD;
#pragma unroll
        for (int j = 0; j < VPT; j++) rowp[tid + j * NT] = v[t][j];
    }
}

// ---------------------------------------------------------------------------
extern "C" void kernel_launch(void* const* d_in, const int* in_sizes, int n_in,
                              void* d_out, int out_size) {
    const float* x     = (const float*)d_in[0];
    const float* W1    = (const float*)d_in[1];
    const float* b1    = (const float*)d_in[2];
    const float* ln1w  = (const float*)d_in[3];
    const float* ln1b  = (const float*)d_in[4];
    const float* beta1 = (const float*)d_in[5];
    const float* W2    = (const float*)d_in[6];
    const float* b2    = (const float*)d_in[7];
    const float* ln2w  = (const float*)d_in[8];
    const float* ln2b  = (const float*)d_in[9];
    const float* beta2 = (const float*)d_in[10];
    float* out = (float*)d_out;

    float *h, *y;
    cudaGetSymbolAddress((void**)&h, g_h);
    cudaGetSymbolAddress((void**)&y, g_y);

    // GEMM1: [32768,512] x [512,2048] + b1 -> h
    {
        dim3 grid(FDIM / 128, MTOT / 128);
        sgemm_bias_128<<<grid, 256>>>(x, W1, b1, h, MTOT, FDIM, DDIM);
    }
    // LN1 + LIF1 (in place: h preacts -> h spikes)
    ln_lif_kernel<FDIM, 256><<<ROWS, 256>>>(h, ln1w, ln1b, beta1, h);

    // GEMM2: [32768,2048] x [2048,512] + b2 -> y
    {
        dim3 grid(DDIM / 128, MTOT / 128);
        sgemm_bias_128<<<grid, 256>>>(h, W2, b2, y, MTOT, DDIM, FDIM);
    }
    // LN2 + LIF2 -> d_out
    ln_lif_kernel<DDIM, 128><<<ROWS, 128>>>(y, ln2w, ln2b, beta2, out);
}